// round 15
// baseline (speedup 1.0000x reference)
#include <cuda_runtime.h>
#include <cuda_bf16.h>
#include <cuda_fp16.h>
#include <mma.h>
#include <cstdint>

using namespace nvcuda;
typedef __nv_bfloat16 bf;

#define NN   50000
#define NE   800000
#define H    128
#define DIN  16
#define DOUT 8
#define NL   4
#define LDB  136
#define LDC  136
#define NPAD 50048   // 782*64

// weight slots (each 16384 elems, row-major [in][out])
#define W_ENCW2     0
#define W_EW1(l,h)  (1 + (l)*2 + (h))
#define W_NW1A(l)   (9 + (l))
#define W_NW2(l)    (13 + (l))
#define W_DECW1     17
#define W_COMB(l)   (18 + (l))
#define NW_TOT      22
#define NW_SPLIT    18
#define W_ELEMS     (NW_TOT * H * H)

// ---------------- persistent device scratch ----------------
__device__ float g_h[NPAD * H];
__device__ __align__(16) __half g_uh[NPAD * H];   // u, half precision (k_edge gather source)
__device__ float g_v[NPAD * H];
__device__ float g_hsum[NPAD * H];
__device__ int   g_rowptr[NN + 1];
__device__ int   g_tmp[NN];          // zero at module load; every launch restores it to zero
__device__ int   g_srcs[NE];
__device__ __align__(16) bf    g_whi[W_ELEMS];
__device__ __align__(16) bf    g_wlo[W_ELEMS];
__device__ __align__(16) float g_bcomb[NL * H];
#define TBL_N 1281
__device__ __align__(16) float2 g_tblg[TBL_N];    // affine: Phi(x) ~= a + b*x on segment i

__device__ __forceinline__ float gelu_f(float v) {
    return 0.5f * v * (1.0f + erff(v * 0.7071067811865476f));
}
__device__ __forceinline__ void split1(float x, bf& h, bf& l) {
    h = __float2bfloat16_rn(x);
    l = __float2bfloat16_rn(x - __bfloat162float(h));
}

// ---------------- Phi PL table, affine form (one-shot) ----------------
__global__ void k_tbl() {
    int i = blockIdx.x * blockDim.x + threadIdx.x;
    if (i < TBL_N) {
        float x0 = -5.f + i * (1.f / 128.f);
        float p0 = 0.5f * (1.f + erff(x0 * 0.70710678f));
        float p1 = 0.5f * (1.f + erff((x0 + (1.f / 128.f)) * 0.70710678f));
        float dp = p1 - p0;
        float a = p0 + (640.f - (float)i) * dp;
        float b = 128.f * dp;
        g_tblg[i] = make_float2(a, b);
    }
}

// ---------------- CSR build (self-restoring g_tmp) ----------------
__global__ void k_count(const int* __restrict__ dst) {
    int e = blockIdx.x * blockDim.x + threadIdx.x;
    if (e < NE) atomicAdd(&g_tmp[dst[e]], 1);
}
#define SCAN_CH 49   // 1024*49 = 50176 >= NN
__global__ __launch_bounds__(1024) void k_scan() {
    __shared__ int s[1024];
    int t = threadIdx.x;
    int base = t * SCAN_CH;
    int loc[SCAN_CH];
    int sum = 0;
    #pragma unroll
    for (int j = 0; j < SCAN_CH; j++) {
        int i = base + j;
        int v = (i < NN) ? g_tmp[i] : 0;
        loc[j] = sum;
        sum += v;
    }
    s[t] = sum;
    __syncthreads();
    #pragma unroll
    for (int off = 1; off < 1024; off <<= 1) {
        int x = (t >= off) ? s[t - off] : 0;
        __syncthreads();
        s[t] += x;
        __syncthreads();
    }
    int carry = (t > 0) ? s[t - 1] : 0;
    #pragma unroll
    for (int j = 0; j < SCAN_CH; j++) {
        int i = base + j;
        if (i < NN) g_rowptr[i] = carry + loc[j];
    }
    if (t == 0) g_rowptr[NN] = s[1023];
}
__global__ void k_fill(const int* __restrict__ src, const int* __restrict__ dst) {
    int e = blockIdx.x * blockDim.x + threadIdx.x;
    if (e < NE) {
        int d = dst[e];
        int slot = atomicSub(&g_tmp[d], 1) - 1;
        g_srcs[g_rowptr[d] + slot] = src[e];
    }
}

// ---------------- weight pre-split ----------------
struct WSrc { const float *encW2, *eW1, *nW1, *nW2, *decW1; };

__global__ void k_split_w(WSrc ws) {
    int i = blockIdx.x * blockDim.x + threadIdx.x;
    if (i >= NW_SPLIT * 16384) return;
    int m = i >> 14, w = i & 16383;
    float x;
    if      (m == 0)  x = ws.encW2[w];
    else if (m <= 8)  { int q = m - 1; x = ws.eW1[(q >> 1) * 32768 + (q & 1) * 16384 + w]; }
    else if (m <= 12) x = ws.nW1[(m - 9) * 32768 + w];
    else if (m <= 16) x = ws.nW2[(m - 13) * 16384 + w];
    else              x = ws.decW1[w];
    bf hh = __float2bfloat16_rn(x);
    g_whi[i] = hh;
    g_wlo[i] = __float2bfloat16_rn(x - __bfloat162float(hh));
}

// ---------------- Wcomb = eW2 @ nW1b ; bcomb = eb2 @ nW1b ----------------
__global__ __launch_bounds__(256) void k_comb(const float* __restrict__ eW2,
                                              const float* __restrict__ nW1,
                                              const float* __restrict__ eb2) {
    extern __shared__ float sm[];
    float* As = sm;
    float* Bs = sm + 16384;
    int l = blockIdx.x, tid = threadIdx.x;
    const float* A = eW2 + (size_t)l * 16384;
    const float* B = nW1 + (size_t)l * 32768 + 16384;
    for (int i = tid; i < 16384; i += 256) { As[i] = A[i]; Bs[i] = B[i]; }
    __syncthreads();
    for (int i = tid; i < 16384; i += 256) {
        int k = i >> 7, n = i & 127;
        float s = 0.f;
        #pragma unroll 8
        for (int m = 0; m < 128; m++) s += As[k * 128 + m] * Bs[m * 128 + n];
        bf hh = __float2bfloat16_rn(s);
        size_t o = (size_t)(W_COMB(l)) * 16384 + i;
        g_whi[o] = hh;
        g_wlo[o] = __float2bfloat16_rn(s - __bfloat162float(hh));
    }
    if (tid < 128) {
        float s = 0.f;
        #pragma unroll 8
        for (int m = 0; m < 128; m++) s += __ldg(eb2 + l * 128 + m) * Bs[m * 128 + tid];
        g_bcomb[l * 128 + tid] = s;
    }
}

// ---------------- smem staging helpers ----------------
__device__ __forceinline__ void copy_Bw(bf* Bhi, bf* Blo, int widx, int tid) {
    const uint4* Sh = (const uint4*)(const void*)(g_whi + (size_t)widx * 16384);
    const uint4* Sl = (const uint4*)(const void*)(g_wlo + (size_t)widx * 16384);
    #pragma unroll 4
    for (int i = tid; i < 2048; i += 256) {
        int r = i >> 4, c8 = (i & 15) << 3;
        *(uint4*)(Bhi + r * LDB + c8) = Sh[i];
        *(uint4*)(Blo + r * LDB + c8) = Sl[i];
    }
}
__device__ __forceinline__ void split_smem4(bf* Ahi, bf* Alo, int idx, float4 v) {
    bf h0, l0, h1, l1, h2, l2, h3, l3;
    split1(v.x, h0, l0); split1(v.y, h1, l1); split1(v.z, h2, l2); split1(v.w, h3, l3);
    uint2 ph, pl;
    ph.x = (uint32_t)__bfloat16_as_ushort(h0) | ((uint32_t)__bfloat16_as_ushort(h1) << 16);
    ph.y = (uint32_t)__bfloat16_as_ushort(h2) | ((uint32_t)__bfloat16_as_ushort(h3) << 16);
    pl.x = (uint32_t)__bfloat16_as_ushort(l0) | ((uint32_t)__bfloat16_as_ushort(l1) << 16);
    pl.y = (uint32_t)__bfloat16_as_ushort(l2) | ((uint32_t)__bfloat16_as_ushort(l3) << 16);
    *(uint2*)(Ahi + idx) = ph;
    *(uint2*)(Alo + idx) = pl;
}
template <int ROWS>
__device__ __forceinline__ void loadsplit_A(bf* Ahi, bf* Alo, const float* __restrict__ src, int tid) {
    const float4* S = (const float4*)src;
    #pragma unroll 4
    for (int i = tid; i < ROWS * 32; i += 256) {
        int r = i >> 5, c4 = (i & 31) << 2;
        float4 t = S[i];
        split_smem4(Ahi, Alo, r * LDB + c4, t);
    }
}
// smem fp32 Cs tile [64 x LDC] -> g_uh half rows at row0
__device__ __forceinline__ void cvt_C_to_uh(const float* Cs, int row0, int tid) {
    for (int i = tid; i < 64 * 32; i += 256) {
        int r = i >> 5, c4 = (i & 31) << 2;
        float4 v = *(const float4*)(Cs + r * LDC + c4);
        __half2 h0 = __floats2half2_rn(v.x, v.y);
        __half2 h1 = __floats2half2_rn(v.z, v.w);
        uint2 pk;
        pk.x = *(uint32_t*)&h0;
        pk.y = *(uint32_t*)&h1;
        *(uint2*)(g_uh + (size_t)(row0 + r) * H + c4) = pk;
    }
}

// ---------------- wmma bf16x3 core (warp tile 16x64, 8 warps -> 64x128) ----------------
typedef wmma::fragment<wmma::matrix_a, 16, 16, 16, bf, wmma::row_major> FA;
typedef wmma::fragment<wmma::matrix_b, 16, 16, 16, bf, wmma::row_major> FB;
typedef wmma::fragment<wmma::accumulator, 16, 16, 16, float> FC;

__device__ __forceinline__ void gemm_bf3(FC (&acc)[4], const bf* Ahi, const bf* Alo,
                                         const bf* Bhi, const bf* Blo, int wr, int wc) {
    #pragma unroll
    for (int k = 0; k < H; k += 16) {
        FA ah, al;
        wmma::load_matrix_sync(ah, Ahi + wr * 16 * LDB + k, LDB);
        wmma::load_matrix_sync(al, Alo + wr * 16 * LDB + k, LDB);
        #pragma unroll
        for (int j = 0; j < 4; j++) {
            FB bh, bl;
            wmma::load_matrix_sync(bh, Bhi + k * LDB + wc * 64 + j * 16, LDB);
            wmma::load_matrix_sync(bl, Blo + k * LDB + wc * 64 + j * 16, LDB);
            wmma::mma_sync(acc[j], al, bh, acc[j]);
            wmma::mma_sync(acc[j], ah, bl, acc[j]);
            wmma::mma_sync(acc[j], ah, bh, acc[j]);
        }
    }
}
__device__ __forceinline__ void fill04(FC (&acc)[4]) {
    #pragma unroll
    for (int j = 0; j < 4; j++) wmma::fill_fragment(acc[j], 0.f);
}
__device__ __forceinline__ void store64s(float* Cs, FC (&acc)[4], int wr, int wc) {
    #pragma unroll
    for (int j = 0; j < 4; j++)
        wmma::store_matrix_sync(Cs + wr * 16 * LDC + wc * 64 + j * 16, acc[j], LDC,
                                wmma::mem_row_major);
}
__device__ __forceinline__ void store64g(float* out, int row0, FC (&acc)[4], int wr, int wc) {
    #pragma unroll
    for (int j = 0; j < 4; j++)
        wmma::store_matrix_sync(out + (size_t)(row0 + wr * 16) * H + wc * 64 + j * 16,
                                acc[j], H, wmma::mem_row_major);
}

// ---------------- encode (+ fused u/v for layer 0) ----------------
__global__ __launch_bounds__(256) void k_encode(const float* __restrict__ x,
                         const float* __restrict__ W1, const float* __restrict__ b1,
                         const float* __restrict__ b2) {
    extern __shared__ char smc[];
    float* xs  = (float*)smc;
    float* W1s = xs + 64 * DIN;
    float* Cs  = W1s + DIN * H;
    bf* Ahi = (bf*)(Cs + 64 * LDC);
    bf* Alo = Ahi + 64 * LDB;
    bf* Bhi = Alo + 64 * LDB;
    bf* Blo = Bhi + 128 * LDB;
    int tid = threadIdx.x, warp = tid >> 5, wr = warp >> 1, wc = warp & 1;
    int row0 = blockIdx.x * 64;

    {
        const float4* X4 = (const float4*)x;
        for (int i = tid; i < 64 * DIN / 4; i += 256) {
            int r = i >> 2, c4 = i & 3;
            int n = row0 + r;
            float4 t = (n < NN) ? X4[n * 4 + c4] : make_float4(0.f, 0.f, 0.f, 0.f);
            *(float4*)(xs + r * DIN + c4 * 4) = t;
        }
        const float4* W4 = (const float4*)W1;
        for (int i = tid; i < DIN * H / 4; i += 256)
            *(float4*)(W1s + i * 4) = W4[i];
    }
    copy_Bw(Bhi, Blo, W_ENCW2, tid);
    __syncthreads();
    for (int i = tid; i < 64 * H; i += 256) {
        int r = i >> 7, c = i & 127;
        float a = __ldg(b1 + c);
        #pragma unroll
        for (int k = 0; k < DIN; k++) a += xs[r * DIN + k] * W1s[k * H + c];
        Cs[r * LDC + c] = gelu_f(a);
    }
    __syncthreads();
    for (int i = tid; i < 64 * 32; i += 256) {
        int r = i >> 5, c4 = (i & 31) << 2;
        float4 v = *(float4*)(Cs + r * LDC + c4);
        split_smem4(Ahi, Alo, r * LDB + c4, v);
    }
    __syncthreads();
    FC acc[4];
    fill04(acc);
    gemm_bf3(acc, Ahi, Alo, Bhi, Blo, wr, wc);
    store64s(Cs, acc, wr, wc);
    __syncthreads();
    for (int i = tid; i < 64 * 32; i += 256) {
        int r = i >> 5, c4 = (i & 31) << 2;
        int n = row0 + r;
        float4 v = *(float4*)(Cs + r * LDC + c4);
        float4 b = *(const float4*)(b2 + c4);
        v.x += b.x; v.y += b.y; v.z += b.z; v.w += b.w;
        if (n >= NN) v = make_float4(0.f, 0.f, 0.f, 0.f);
        *(float4*)(g_h + (size_t)n * H + c4) = v;
        split_smem4(Ahi, Alo, r * LDB + c4, v);
    }
    copy_Bw(Bhi, Blo, W_EW1(0, 0), tid);
    __syncthreads();
    {
        FC a2[4];
        fill04(a2);
        gemm_bf3(a2, Ahi, Alo, Bhi, Blo, wr, wc);
        store64s(Cs, a2, wr, wc);
    }
    __syncthreads();
    cvt_C_to_uh(Cs, row0, tid);
    __syncthreads();
    copy_Bw(Bhi, Blo, W_EW1(0, 1), tid);
    __syncthreads();
    {
        FC a2[4];
        fill04(a2);
        gemm_bf3(a2, Ahi, Alo, Bhi, Blo, wr, wc);
        store64g(g_v, row0, a2, wr, wc);
    }
}

// ---------------- edge: hsum[n] = sum_{s in seg(n)} gelu(u[s]+v[n]+b1) ----------------
// affine PL table evaluated at xc = clamp(x, -5, 5): Phi(xc) ~= a_i + b_i*xc; gelu = x*Phi.
// Tails: x>5 -> Phi~1 -> gelu~x; x<-5 -> Phi~2.9e-7 -> gelu~0. No extrapolation blow-up.
__device__ __forceinline__ float gelu_t(float x, const float2* __restrict__ tbl) {
    float xc = fminf(fmaxf(x, -5.f), 5.f);
    float t = fmaf(xc, 128.f, 640.f);          // in [0, 1280]
    int i = (int)fminf(t, 1279.f);
    float2 e = tbl[i];
    return x * fmaf(e.y, xc, e.x);
}
__device__ __forceinline__ void acc_edge(float4& acc, uint2 r, const float4& vv,
                                         const float2* __restrict__ tbl) {
    float2 f0 = __half22float2(*(__half2*)&r.x);
    float2 f1 = __half22float2(*(__half2*)&r.y);
    acc.x += gelu_t(f0.x + vv.x, tbl);
    acc.y += gelu_t(f0.y + vv.y, tbl);
    acc.z += gelu_t(f1.x + vv.z, tbl);
    acc.w += gelu_t(f1.y + vv.w, tbl);
}

__global__ void k_edge(const float* __restrict__ eb1) {
    __shared__ float2 tbl[TBL_N];
    int tid = threadIdx.x;
    for (int i = tid; i < TBL_N; i += 256) tbl[i] = g_tblg[i];
    __syncthreads();

    int w = (blockIdx.x * blockDim.x + tid) >> 5;
    int lane = tid & 31;
    if (w >= NPAD) return;
    size_t hoff = (size_t)w * H;
    if (w >= NN) {
        ((float4*)(g_hsum + hoff))[lane] = make_float4(0.f, 0.f, 0.f, 0.f);
        return;
    }
    float4 vv = ((const float4*)(g_v + hoff))[lane];
    float4 bb = ((const float4*)eb1)[lane];
    vv.x += bb.x; vv.y += bb.y; vv.z += bb.z; vv.w += bb.w;
    float4 acc = make_float4(0.f, 0.f, 0.f, 0.f);
    int p0  = g_rowptr[w];
    int deg = g_rowptr[w + 1] - p0;

    for (int base = 0; base < deg; base += 32) {
        int m = min(32, deg - base);
        int id = (base + lane < deg) ? __ldg(g_srcs + p0 + base + lane) : 0;
        int j = 0;
        for (; j + 8 <= m; j += 8) {
            int s0 = __shfl_sync(0xFFFFFFFFu, id, j);
            int s1 = __shfl_sync(0xFFFFFFFFu, id, j + 1);
            int s2 = __shfl_sync(0xFFFFFFFFu, id, j + 2);
            int s3 = __shfl_sync(0xFFFFFFFFu, id, j + 3);
            int s4 = __shfl_sync(0xFFFFFFFFu, id, j + 4);
            int s5 = __shfl_sync(0xFFFFFFFFu, id, j + 5);
            int s6 = __shfl_sync(0xFFFFFFFFu, id, j + 6);
            int s7 = __shfl_sync(0xFFFFFFFFu, id, j + 7);
            uint2 r0 = ((const uint2*)(g_uh + (size_t)s0 * H))[lane];
            uint2 r1 = ((const uint2*)(g_uh + (size_t)s1 * H))[lane];
            uint2 r2 = ((const uint2*)(g_uh + (size_t)s2 * H))[lane];
            uint2 r3 = ((const uint2*)(g_uh + (size_t)s3 * H))[lane];
            uint2 r4 = ((const uint2*)(g_uh + (size_t)s4 * H))[lane];
            uint2 r5 = ((const uint2*)(g_uh + (size_t)s5 * H))[lane];
            uint2 r6 = ((const uint2*)(g_uh + (size_t)s6 * H))[lane];
            uint2 r7 = ((const uint2*)(g_uh + (size_t)s7 * H))[lane];
            acc_edge(acc, r0, vv, tbl);
            acc_edge(acc, r1, vv, tbl);
            acc_edge(acc, r2, vv, tbl);
            acc_edge(acc, r3, vv, tbl);
            acc_edge(acc, r4, vv, tbl);
            acc_edge(acc, r5, vv, tbl);
            acc_edge(acc, r6, vv, tbl);
            acc_edge(acc, r7, vv, tbl);
        }
        for (; j < m; j++) {
            int s0 = __shfl_sync(0xFFFFFFFFu, id, j);
            uint2 r0 = ((const uint2*)(g_uh + (size_t)s0 * H))[lane];
            acc_edge(acc, r0, vv, tbl);
        }
    }
    ((float4*)(g_hsum + hoff))[lane] = acc;
}

// ---------------- fused per-layer node kernel: BM=64, 2 CTAs/SM ----------------
// smem: [0, 34816) A split | [34816, 104448) B split (Cs fp32 aliases here) | [104448, 108544) W2s
#define P2_OFF_B   34816
#define P2_OFF_W2S 104448
#define P2_SMEM    108544

__global__ __launch_bounds__(256, 2) void k_p2(
    int l, const float* __restrict__ nb1, const float* __restrict__ nb2,
    int w_nW1a, int w_nW2, int w_comb, int w_uv_next,
    const float* __restrict__ db1, const float* __restrict__ dW2,
    const float* __restrict__ db2, float* __restrict__ out) {
    extern __shared__ char smc[];
    bf* Ahi = (bf*)smc;                        // 64 x LDB
    bf* Alo = Ahi + 64 * LDB;
    bf* Bhi = (bf*)(smc + P2_OFF_B);           // 128 x LDB
    bf* Blo = Bhi + 128 * LDB;
    float* Cs  = (float*)(smc + P2_OFF_B);     // 64 x LDC, ALIASES B (used only between gemms)
    float* W2s = (float*)(smc + P2_OFF_W2S);   // 128 x 8
    int tid = threadIdx.x, wid = tid >> 5, wr = wid >> 1, wc = wid & 1;
    int row0 = blockIdx.x * 64;

    // Stage A: acc = h@nW1a
    loadsplit_A<64>(Ahi, Alo, g_h + (size_t)row0 * H, tid);
    copy_Bw(Bhi, Blo, w_nW1a, tid);
    __syncthreads();
    FC acc[4];
    fill04(acc);
    gemm_bf3(acc, Ahi, Alo, Bhi, Blo, wr, wc);
    __syncthreads();
    // Stage B: acc += hsum@Wcomb
    loadsplit_A<64>(Ahi, Alo, g_hsum + (size_t)row0 * H, tid);
    copy_Bw(Bhi, Blo, w_comb, tid);
    __syncthreads();
    gemm_bf3(acc, Ahi, Alo, Bhi, Blo, wr, wc);
    __syncthreads();                            // done reading B -> Cs may overwrite
    store64s(Cs, acc, wr, wc);
    __syncthreads();
    // G = gelu(acc + deg*bcomb + nb1) -> A split
    for (int i = tid; i < 64 * 32; i += 256) {
        int r = i >> 5, c4 = (i & 31) << 2;
        int n = row0 + r;
        float d = (n < NN) ? (float)(g_rowptr[n + 1] - g_rowptr[n]) : 0.f;
        float4 v  = *(float4*)(Cs + r * LDC + c4);
        float4 bc = *(const float4*)(g_bcomb + l * H + c4);
        float4 b1 = *(const float4*)(nb1 + c4);
        v.x = gelu_f(v.x + d * bc.x + b1.x);
        v.y = gelu_f(v.y + d * bc.y + b1.y);
        v.z = gelu_f(v.z + d * bc.z + b1.z);
        v.w = gelu_f(v.w + d * bc.w + b1.w);
        split_smem4(Ahi, Alo, r * LDB + c4, v);
    }
    __syncthreads();                            // Cs read done -> B may overwrite
    // Stage C: upd = G@nW2
    copy_Bw(Bhi, Blo, w_nW2, tid);
    __syncthreads();
    fill04(acc);
    gemm_bf3(acc, Ahi, Alo, Bhi, Blo, wr, wc);
    __syncthreads();
    store64s(Cs, acc, wr, wc);
    __syncthreads();
    // hnew = h + upd + nb2 -> g_h, A split
    for (int i = tid; i < 64 * 32; i += 256) {
        int r = i >> 5, c4 = (i & 31) << 2;
        size_t off = (size_t)(row0 + r) * H + c4;
        float4 v  = *(float4*)(Cs + r * LDC + c4);
        float4 ho = *(const float4*)(g_h + off);
        float4 b2 = *(const float4*)(nb2 + c4);
        v.x += ho.x + b2.x; v.y += ho.y + b2.y;
        v.z += ho.z + b2.z; v.w += ho.w + b2.w;
        *(float4*)(g_h + off) = v;
        split_smem4(Ahi, Alo, r * LDB + c4, v);
    }
    __syncthreads();

    if (w_uv_next >= 0) {
        // u = hnew@eW1a -> g_uh (half)
        copy_Bw(Bhi, Blo, w_uv_next, tid);
        __syncthreads();
        FC a2[4];
        fill04(a2);
        gemm_bf3(a2, Ahi, Alo, Bhi, Blo, wr, wc);
        __syncthreads();                        // all warps done reading B
        store64s(Cs, a2, wr, wc);
        __syncthreads();
        cvt_C_to_uh(Cs, row0, tid);
        __syncthreads();                        // convert reads done -> B may overwrite
        // v = hnew@eW1b -> g_v (fp32)
        copy_Bw(Bhi, Blo, w_uv_next + 1, tid);
        __syncthreads();
        fill04(a2);
        gemm_bf3(a2, Ahi, Alo, Bhi, Blo, wr, wc);
        store64g(g_v, row0, a2, wr, wc);
    } else {
        // decode: hid = gelu(hnew@dW1 + db1); out = hid@dW2 + db2
        copy_Bw(Bhi, Blo, W_DECW1, tid);
        for (int i = tid; i < H * DOUT / 4; i += 256)
            *(float4*)(W2s + i * 4) = *(const float4*)(dW2 + i * 4);
        __syncthreads();
        fill04(acc);
        gemm_bf3(acc, Ahi, Alo, Bhi, Blo, wr, wc);
        __syncthreads();
        store64s(Cs, acc, wr, wc);
        __syncthreads();
        for (int i = tid; i < 64 * H; i += 256) {
            int r = i >> 7, c = i & 127;
            Cs[r * LDC + c] = gelu_f(Cs[r * LDC + c] + __ldg(db1 + c));
        }
        __syncthreads();
        for (int i = tid; i < 64 * DOUT; i += 256) {
            int r = i >> 3, o = i & 7;
            int n = row0 + r;
            if (n >= NN) continue;
            float a = __ldg(db2 + o);
            #pragma unroll 16
            for (int k = 0; k < H; k++) a += Cs[r * LDC + k] * W2s[k * DOUT + o];
            out[n * DOUT + o] = a;
        }
    }
}

// ---------------- launch ----------------
#define ENC_SMEM  ((64*DIN + DIN*H + 64*LDC) * 4 + (2*64 + 2*128) * LDB * 2)
#define COMB_SMEM (2 * 16384 * 4)

extern "C" void kernel_launch(void* const* d_in, const int* in_sizes, int n_in,
                              void* d_out, int out_size) {
    const float* x     = (const float*)d_in[0];
    const int*   ei    = (const int*)d_in[1];
    const float* encW1 = (const float*)d_in[2];
    const float* encb1 = (const float*)d_in[3];
    const float* encW2 = (const float*)d_in[4];
    const float* encb2 = (const float*)d_in[5];
    const float* eW1   = (const float*)d_in[6];
    const float* eb1   = (const float*)d_in[7];
    const float* eW2   = (const float*)d_in[8];
    const float* eb2   = (const float*)d_in[9];
    const float* nW1   = (const float*)d_in[10];
    const float* nb1   = (const float*)d_in[11];
    const float* nW2   = (const float*)d_in[12];
    const float* nb2   = (const float*)d_in[13];
    const float* dW1   = (const float*)d_in[14];
    const float* db1   = (const float*)d_in[15];
    const float* dW2   = (const float*)d_in[16];
    const float* db2   = (const float*)d_in[17];
    float* out = (float*)d_out;

    cudaFuncSetAttribute(k_encode, cudaFuncAttributeMaxDynamicSharedMemorySize, ENC_SMEM);
    cudaFuncSetAttribute(k_p2,     cudaFuncAttributeMaxDynamicSharedMemorySize, P2_SMEM);
    cudaFuncSetAttribute(k_comb,   cudaFuncAttributeMaxDynamicSharedMemorySize, COMB_SMEM);

    const int* src = ei;
    const int* dst = ei + NE;

    // launches: 1 count, 2 scan, 3 fill, 4 k_p2 PROBE (ncu lands on my 4th kernel)
    k_count<<<(NE + 255) / 256, 256>>>(dst);
    k_scan<<<1, 1024>>>();
    k_fill<<<(NE + 255) / 256, 256>>>(src, dst);

    // PROFILING PROBE: one wave of k_p2 (296 blocks = 2/SM) on stale-but-shaped state.
    // Writes g_h/g_uh/g_v only — all fully overwritten by k_encode below.
    k_p2<<<296, 256, P2_SMEM>>>(0, nb1, nb2, W_NW1A(0), W_NW2(0), W_COMB(0), W_EW1(1, 0),
                                db1, dW2, db2, out);

    k_tbl<<<(TBL_N + 255) / 256, 256>>>();

    WSrc ws{encW2, eW1, nW1, nW2, dW1};
    k_split_w<<<(NW_SPLIT * 16384 + 255) / 256, 256>>>(ws);

    k_encode<<<NPAD / 64, 256, ENC_SMEM>>>(x, encW1, encb1, encb2);

    for (int l = 0; l < NL; l++) {
        k_edge<<<NPAD / 8, 256>>>(eb1 + (size_t)l * H);
        if (l == 0) k_comb<<<NL, 256, COMB_SMEM>>>(eW2, nW1, eb2);
        bool last = (l == NL - 1);
        k_p2<<<NPAD / 64, 256, P2_SMEM>>>(
            l, nb1 + (size_t)l * H, nb2 + (size_t)l * H,
            W_NW1A(l), W_NW2(l), W_COMB(l),
            last ? -1 : W_EW1(l + 1, 0),
            db1, dW2, db2, out);
    }
}

// round 17
// speedup vs baseline: 1.1218x; 1.1218x over previous
#include <cuda_runtime.h>
#include <cuda_bf16.h>
#include <cuda_fp16.h>
#include <mma.h>
#include <cstdint>

using namespace nvcuda;
typedef __nv_bfloat16 bf;

#define NN   50000
#define NE   800000
#define H    128
#define DIN  16
#define DOUT 8
#define NL   4
#define LDB  136
#define LDC  136
#define NPAD 50048   // 782*64

// weight slots (each 16384 elems, row-major [in][out])
#define W_ENCW2     0
#define W_EW1(l,h)  (1 + (l)*2 + (h))
#define W_NW1A(l)   (9 + (l))
#define W_NW2(l)    (13 + (l))
#define W_DECW1     17
#define W_COMB(l)   (18 + (l))
#define NW_TOT      22
#define NW_SPLIT    18
#define W_ELEMS     (NW_TOT * H * H)

// ---------------- persistent device scratch ----------------
__device__ float g_h[NPAD * H];
__device__ __align__(16) __half g_uh[NPAD * H];   // u, half precision (k_edge gather source)
__device__ float g_v[NPAD * H];
__device__ float g_hsum[NPAD * H];
__device__ int   g_rowptr[NN + 1];
__device__ int   g_tmp[NN];          // zero at module load; every launch restores it to zero
__device__ int   g_srcs[NE];
__device__ __align__(16) bf    g_whi[W_ELEMS];
__device__ __align__(16) bf    g_wlo[W_ELEMS];
__device__ __align__(16) float g_bcomb[NL * H];
#define TBL_N 1281
__device__ __align__(16) float2 g_tblg[TBL_N];    // affine: Phi(x) ~= a + b*x on segment i

__device__ __forceinline__ float gelu_f(float v) {
    return 0.5f * v * (1.0f + erff(v * 0.7071067811865476f));
}
__device__ __forceinline__ void split1(float x, bf& h, bf& l) {
    h = __float2bfloat16_rn(x);
    l = __float2bfloat16_rn(x - __bfloat162float(h));
}

// ---------------- Phi PL table, affine form (one-shot) ----------------
__global__ void k_tbl() {
    int i = blockIdx.x * blockDim.x + threadIdx.x;
    if (i < TBL_N) {
        float x0 = -5.f + i * (1.f / 128.f);
        float p0 = 0.5f * (1.f + erff(x0 * 0.70710678f));
        float p1 = 0.5f * (1.f + erff((x0 + (1.f / 128.f)) * 0.70710678f));
        float dp = p1 - p0;
        float a = p0 + (640.f - (float)i) * dp;
        float b = 128.f * dp;
        g_tblg[i] = make_float2(a, b);
    }
}

// ---------------- CSR build (self-restoring g_tmp) ----------------
__global__ void k_count(const int* __restrict__ dst) {
    int e = blockIdx.x * blockDim.x + threadIdx.x;
    if (e < NE) atomicAdd(&g_tmp[dst[e]], 1);
}
#define SCAN_CH 49   // 1024*49 = 50176 >= NN
__global__ __launch_bounds__(1024) void k_scan() {
    __shared__ int s[1024];
    int t = threadIdx.x;
    int base = t * SCAN_CH;
    int loc[SCAN_CH];
    int sum = 0;
    #pragma unroll
    for (int j = 0; j < SCAN_CH; j++) {
        int i = base + j;
        int v = (i < NN) ? g_tmp[i] : 0;
        loc[j] = sum;
        sum += v;
    }
    s[t] = sum;
    __syncthreads();
    #pragma unroll
    for (int off = 1; off < 1024; off <<= 1) {
        int x = (t >= off) ? s[t - off] : 0;
        __syncthreads();
        s[t] += x;
        __syncthreads();
    }
    int carry = (t > 0) ? s[t - 1] : 0;
    #pragma unroll
    for (int j = 0; j < SCAN_CH; j++) {
        int i = base + j;
        if (i < NN) g_rowptr[i] = carry + loc[j];
    }
    if (t == 0) g_rowptr[NN] = s[1023];
}
__global__ void k_fill(const int* __restrict__ src, const int* __restrict__ dst) {
    int e = blockIdx.x * blockDim.x + threadIdx.x;
    if (e < NE) {
        int d = dst[e];
        int slot = atomicSub(&g_tmp[d], 1) - 1;
        g_srcs[g_rowptr[d] + slot] = src[e];
    }
}

// ---------------- weight pre-split ----------------
struct WSrc { const float *encW2, *eW1, *nW1, *nW2, *decW1; };

__global__ void k_split_w(WSrc ws) {
    int i = blockIdx.x * blockDim.x + threadIdx.x;
    if (i >= NW_SPLIT * 16384) return;
    int m = i >> 14, w = i & 16383;
    float x;
    if      (m == 0)  x = ws.encW2[w];
    else if (m <= 8)  { int q = m - 1; x = ws.eW1[(q >> 1) * 32768 + (q & 1) * 16384 + w]; }
    else if (m <= 12) x = ws.nW1[(m - 9) * 32768 + w];
    else if (m <= 16) x = ws.nW2[(m - 13) * 16384 + w];
    else              x = ws.decW1[w];
    bf hh = __float2bfloat16_rn(x);
    g_whi[i] = hh;
    g_wlo[i] = __float2bfloat16_rn(x - __bfloat162float(hh));
}

// ---------------- Wcomb = eW2 @ nW1b ; bcomb = eb2 @ nW1b ----------------
__global__ __launch_bounds__(256) void k_comb(const float* __restrict__ eW2,
                                              const float* __restrict__ nW1,
                                              const float* __restrict__ eb2) {
    extern __shared__ float sm[];
    float* As = sm;
    float* Bs = sm + 16384;
    int l = blockIdx.x, tid = threadIdx.x;
    const float* A = eW2 + (size_t)l * 16384;
    const float* B = nW1 + (size_t)l * 32768 + 16384;
    for (int i = tid; i < 16384; i += 256) { As[i] = A[i]; Bs[i] = B[i]; }
    __syncthreads();
    for (int i = tid; i < 16384; i += 256) {
        int k = i >> 7, n = i & 127;
        float s = 0.f;
        #pragma unroll 8
        for (int m = 0; m < 128; m++) s += As[k * 128 + m] * Bs[m * 128 + n];
        bf hh = __float2bfloat16_rn(s);
        size_t o = (size_t)(W_COMB(l)) * 16384 + i;
        g_whi[o] = hh;
        g_wlo[o] = __float2bfloat16_rn(s - __bfloat162float(hh));
    }
    if (tid < 128) {
        float s = 0.f;
        #pragma unroll 8
        for (int m = 0; m < 128; m++) s += __ldg(eb2 + l * 128 + m) * Bs[m * 128 + tid];
        g_bcomb[l * 128 + tid] = s;
    }
}

// ---------------- smem staging helpers ----------------
__device__ __forceinline__ void copy_Bw(bf* Bhi, bf* Blo, int widx, int tid) {
    const uint4* Sh = (const uint4*)(const void*)(g_whi + (size_t)widx * 16384);
    const uint4* Sl = (const uint4*)(const void*)(g_wlo + (size_t)widx * 16384);
    #pragma unroll 4
    for (int i = tid; i < 2048; i += 256) {
        int r = i >> 4, c8 = (i & 15) << 3;
        *(uint4*)(Bhi + r * LDB + c8) = Sh[i];
        *(uint4*)(Blo + r * LDB + c8) = Sl[i];
    }
}
__device__ __forceinline__ void split_smem4(bf* Ahi, bf* Alo, int idx, float4 v) {
    bf h0, l0, h1, l1, h2, l2, h3, l3;
    split1(v.x, h0, l0); split1(v.y, h1, l1); split1(v.z, h2, l2); split1(v.w, h3, l3);
    uint2 ph, pl;
    ph.x = (uint32_t)__bfloat16_as_ushort(h0) | ((uint32_t)__bfloat16_as_ushort(h1) << 16);
    ph.y = (uint32_t)__bfloat16_as_ushort(h2) | ((uint32_t)__bfloat16_as_ushort(h3) << 16);
    pl.x = (uint32_t)__bfloat16_as_ushort(l0) | ((uint32_t)__bfloat16_as_ushort(l1) << 16);
    pl.y = (uint32_t)__bfloat16_as_ushort(l2) | ((uint32_t)__bfloat16_as_ushort(l3) << 16);
    *(uint2*)(Ahi + idx) = ph;
    *(uint2*)(Alo + idx) = pl;
}
template <int ROWS>
__device__ __forceinline__ void loadsplit_A(bf* Ahi, bf* Alo, const float* __restrict__ src, int tid) {
    const float4* S = (const float4*)src;
    #pragma unroll 4
    for (int i = tid; i < ROWS * 32; i += 256) {
        int r = i >> 5, c4 = (i & 31) << 2;
        float4 t = S[i];
        split_smem4(Ahi, Alo, r * LDB + c4, t);
    }
}
// smem fp32 Cs tile [64 x LDC] -> g_uh half rows at row0
__device__ __forceinline__ void cvt_C_to_uh(const float* Cs, int row0, int tid) {
    for (int i = tid; i < 64 * 32; i += 256) {
        int r = i >> 5, c4 = (i & 31) << 2;
        float4 v = *(const float4*)(Cs + r * LDC + c4);
        __half2 h0 = __floats2half2_rn(v.x, v.y);
        __half2 h1 = __floats2half2_rn(v.z, v.w);
        uint2 pk;
        pk.x = *(uint32_t*)&h0;
        pk.y = *(uint32_t*)&h1;
        *(uint2*)(g_uh + (size_t)(row0 + r) * H + c4) = pk;
    }
}

// ---------------- wmma bf16x3 cores ----------------
typedef wmma::fragment<wmma::matrix_a, 16, 16, 16, bf, wmma::row_major> FA;
typedef wmma::fragment<wmma::matrix_b, 16, 16, 16, bf, wmma::row_major> FB;
typedef wmma::fragment<wmma::accumulator, 16, 16, 16, float> FC;

// encode-path core: warp tile 16x64 (wr 0..3, wc 0..1)
__device__ __forceinline__ void gemm_bf3(FC (&acc)[4], const bf* Ahi, const bf* Alo,
                                         const bf* Bhi, const bf* Blo, int wr, int wc) {
    #pragma unroll
    for (int k = 0; k < H; k += 16) {
        FA ah, al;
        wmma::load_matrix_sync(ah, Ahi + wr * 16 * LDB + k, LDB);
        wmma::load_matrix_sync(al, Alo + wr * 16 * LDB + k, LDB);
        #pragma unroll
        for (int j = 0; j < 4; j++) {
            FB bh, bl;
            wmma::load_matrix_sync(bh, Bhi + k * LDB + wc * 64 + j * 16, LDB);
            wmma::load_matrix_sync(bl, Blo + k * LDB + wc * 64 + j * 16, LDB);
            wmma::mma_sync(acc[j], al, bh, acc[j]);
            wmma::mma_sync(acc[j], ah, bl, acc[j]);
            wmma::mma_sync(acc[j], ah, bh, acc[j]);
        }
    }
}
__device__ __forceinline__ void fill04(FC (&acc)[4]) {
    #pragma unroll
    for (int j = 0; j < 4; j++) wmma::fill_fragment(acc[j], 0.f);
}
__device__ __forceinline__ void store64s(float* Cs, FC (&acc)[4], int wr, int wc) {
    #pragma unroll
    for (int j = 0; j < 4; j++)
        wmma::store_matrix_sync(Cs + wr * 16 * LDC + wc * 64 + j * 16, acc[j], LDC,
                                wmma::mem_row_major);
}
__device__ __forceinline__ void store64g(float* out, int row0, FC (&acc)[4], int wr, int wc) {
    #pragma unroll
    for (int j = 0; j < 4; j++)
        wmma::store_matrix_sync(out + (size_t)(row0 + wr * 16) * H + wc * 64 + j * 16,
                                acc[j], H, wmma::mem_row_major);
}

// k_p2 core: warp tile 32x32 (wr 0..1, wc 0..3) — minimizes inter-warp fragment re-loads
__device__ __forceinline__ void gemm_p2(FC (&acc)[2][2], const bf* Ahi, const bf* Alo,
                                        const bf* Bhi, const bf* Blo, int wr, int wc) {
    #pragma unroll
    for (int k = 0; k < H; k += 16) {
        FA ah[2], al[2];
        #pragma unroll
        for (int rr = 0; rr < 2; rr++) {
            wmma::load_matrix_sync(ah[rr], Ahi + (wr * 32 + rr * 16) * LDB + k, LDB);
            wmma::load_matrix_sync(al[rr], Alo + (wr * 32 + rr * 16) * LDB + k, LDB);
        }
        #pragma unroll
        for (int j = 0; j < 2; j++) {
            FB bh, bl;
            wmma::load_matrix_sync(bh, Bhi + k * LDB + wc * 32 + j * 16, LDB);
            wmma::load_matrix_sync(bl, Blo + k * LDB + wc * 32 + j * 16, LDB);
            #pragma unroll
            for (int rr = 0; rr < 2; rr++) {
                wmma::mma_sync(acc[rr][j], al[rr], bh, acc[rr][j]);
                wmma::mma_sync(acc[rr][j], ah[rr], bl, acc[rr][j]);
                wmma::mma_sync(acc[rr][j], ah[rr], bh, acc[rr][j]);
            }
        }
    }
}
__device__ __forceinline__ void fillp2(FC (&acc)[2][2]) {
    #pragma unroll
    for (int rr = 0; rr < 2; rr++)
        #pragma unroll
        for (int j = 0; j < 2; j++) wmma::fill_fragment(acc[rr][j], 0.f);
}
__device__ __forceinline__ void store_p2s(float* Cs, FC (&acc)[2][2], int wr, int wc) {
    #pragma unroll
    for (int rr = 0; rr < 2; rr++)
        #pragma unroll
        for (int j = 0; j < 2; j++)
            wmma::store_matrix_sync(Cs + (wr * 32 + rr * 16) * LDC + wc * 32 + j * 16,
                                    acc[rr][j], LDC, wmma::mem_row_major);
}
__device__ __forceinline__ void store_p2g(float* out, int row0, FC (&acc)[2][2], int wr, int wc) {
    #pragma unroll
    for (int rr = 0; rr < 2; rr++)
        #pragma unroll
        for (int j = 0; j < 2; j++)
            wmma::store_matrix_sync(out + (size_t)(row0 + wr * 32 + rr * 16) * H + wc * 32 + j * 16,
                                    acc[rr][j], H, wmma::mem_row_major);
}

// ---------------- encode (+ fused u/v for layer 0) ----------------
__global__ __launch_bounds__(256) void k_encode(const float* __restrict__ x,
                         const float* __restrict__ W1, const float* __restrict__ b1,
                         const float* __restrict__ b2) {
    extern __shared__ char smc[];
    float* xs  = (float*)smc;
    float* W1s = xs + 64 * DIN;
    float* Cs  = W1s + DIN * H;
    bf* Ahi = (bf*)(Cs + 64 * LDC);
    bf* Alo = Ahi + 64 * LDB;
    bf* Bhi = Alo + 64 * LDB;
    bf* Blo = Bhi + 128 * LDB;
    int tid = threadIdx.x, warp = tid >> 5, wr = warp >> 1, wc = warp & 1;
    int row0 = blockIdx.x * 64;

    {
        const float4* X4 = (const float4*)x;
        for (int i = tid; i < 64 * DIN / 4; i += 256) {
            int r = i >> 2, c4 = i & 3;
            int n = row0 + r;
            float4 t = (n < NN) ? X4[n * 4 + c4] : make_float4(0.f, 0.f, 0.f, 0.f);
            *(float4*)(xs + r * DIN + c4 * 4) = t;
        }
        const float4* W4 = (const float4*)W1;
        for (int i = tid; i < DIN * H / 4; i += 256)
            *(float4*)(W1s + i * 4) = W4[i];
    }
    copy_Bw(Bhi, Blo, W_ENCW2, tid);
    __syncthreads();
    for (int i = tid; i < 64 * H; i += 256) {
        int r = i >> 7, c = i & 127;
        float a = __ldg(b1 + c);
        #pragma unroll
        for (int k = 0; k < DIN; k++) a += xs[r * DIN + k] * W1s[k * H + c];
        Cs[r * LDC + c] = gelu_f(a);
    }
    __syncthreads();
    for (int i = tid; i < 64 * 32; i += 256) {
        int r = i >> 5, c4 = (i & 31) << 2;
        float4 v = *(float4*)(Cs + r * LDC + c4);
        split_smem4(Ahi, Alo, r * LDB + c4, v);
    }
    __syncthreads();
    FC acc[4];
    fill04(acc);
    gemm_bf3(acc, Ahi, Alo, Bhi, Blo, wr, wc);
    store64s(Cs, acc, wr, wc);
    __syncthreads();
    for (int i = tid; i < 64 * 32; i += 256) {
        int r = i >> 5, c4 = (i & 31) << 2;
        int n = row0 + r;
        float4 v = *(float4*)(Cs + r * LDC + c4);
        float4 b = *(const float4*)(b2 + c4);
        v.x += b.x; v.y += b.y; v.z += b.z; v.w += b.w;
        if (n >= NN) v = make_float4(0.f, 0.f, 0.f, 0.f);
        *(float4*)(g_h + (size_t)n * H + c4) = v;
        split_smem4(Ahi, Alo, r * LDB + c4, v);
    }
    copy_Bw(Bhi, Blo, W_EW1(0, 0), tid);
    __syncthreads();
    {
        FC a2[4];
        fill04(a2);
        gemm_bf3(a2, Ahi, Alo, Bhi, Blo, wr, wc);
        store64s(Cs, a2, wr, wc);
    }
    __syncthreads();
    cvt_C_to_uh(Cs, row0, tid);
    __syncthreads();
    copy_Bw(Bhi, Blo, W_EW1(0, 1), tid);
    __syncthreads();
    {
        FC a2[4];
        fill04(a2);
        gemm_bf3(a2, Ahi, Alo, Bhi, Blo, wr, wc);
        store64g(g_v, row0, a2, wr, wc);
    }
}

// ---------------- edge: hsum[n] = sum_{s in seg(n)} gelu(u[s]+v[n]+b1) ----------------
__device__ __forceinline__ float gelu_t(float x, const float2* __restrict__ tbl) {
    float xc = fminf(fmaxf(x, -5.f), 5.f);
    float t = fmaf(xc, 128.f, 640.f);          // in [0, 1280]
    int i = (int)fminf(t, 1279.f);
    float2 e = tbl[i];
    return x * fmaf(e.y, xc, e.x);
}
__device__ __forceinline__ void acc_edge(float4& acc, uint2 r, const float4& vv,
                                         const float2* __restrict__ tbl) {
    float2 f0 = __half22float2(*(__half2*)&r.x);
    float2 f1 = __half22float2(*(__half2*)&r.y);
    acc.x += gelu_t(f0.x + vv.x, tbl);
    acc.y += gelu_t(f0.y + vv.y, tbl);
    acc.z += gelu_t(f1.x + vv.z, tbl);
    acc.w += gelu_t(f1.y + vv.w, tbl);
}

__global__ void k_edge(const float* __restrict__ eb1) {
    __shared__ float2 tbl[TBL_N];
    int tid = threadIdx.x;
    for (int i = tid; i < TBL_N; i += 256) tbl[i] = g_tblg[i];
    __syncthreads();

    int w = (blockIdx.x * blockDim.x + tid) >> 5;
    int lane = tid & 31;
    if (w >= NPAD) return;
    size_t hoff = (size_t)w * H;
    if (w >= NN) {
        ((float4*)(g_hsum + hoff))[lane] = make_float4(0.f, 0.f, 0.f, 0.f);
        return;
    }
    float4 vv = ((const float4*)(g_v + hoff))[lane];
    float4 bb = ((const float4*)eb1)[lane];
    vv.x += bb.x; vv.y += bb.y; vv.z += bb.z; vv.w += bb.w;
    float4 acc = make_float4(0.f, 0.f, 0.f, 0.f);
    int p0  = g_rowptr[w];
    int deg = g_rowptr[w + 1] - p0;

    for (int base = 0; base < deg; base += 32) {
        int m = min(32, deg - base);
        int id = (base + lane < deg) ? __ldg(g_srcs + p0 + base + lane) : 0;
        int j = 0;
        for (; j + 8 <= m; j += 8) {
            int s0 = __shfl_sync(0xFFFFFFFFu, id, j);
            int s1 = __shfl_sync(0xFFFFFFFFu, id, j + 1);
            int s2 = __shfl_sync(0xFFFFFFFFu, id, j + 2);
            int s3 = __shfl_sync(0xFFFFFFFFu, id, j + 3);
            int s4 = __shfl_sync(0xFFFFFFFFu, id, j + 4);
            int s5 = __shfl_sync(0xFFFFFFFFu, id, j + 5);
            int s6 = __shfl_sync(0xFFFFFFFFu, id, j + 6);
            int s7 = __shfl_sync(0xFFFFFFFFu, id, j + 7);
            uint2 r0 = ((const uint2*)(g_uh + (size_t)s0 * H))[lane];
            uint2 r1 = ((const uint2*)(g_uh + (size_t)s1 * H))[lane];
            uint2 r2 = ((const uint2*)(g_uh + (size_t)s2 * H))[lane];
            uint2 r3 = ((const uint2*)(g_uh + (size_t)s3 * H))[lane];
            uint2 r4 = ((const uint2*)(g_uh + (size_t)s4 * H))[lane];
            uint2 r5 = ((const uint2*)(g_uh + (size_t)s5 * H))[lane];
            uint2 r6 = ((const uint2*)(g_uh + (size_t)s6 * H))[lane];
            uint2 r7 = ((const uint2*)(g_uh + (size_t)s7 * H))[lane];
            acc_edge(acc, r0, vv, tbl);
            acc_edge(acc, r1, vv, tbl);
            acc_edge(acc, r2, vv, tbl);
            acc_edge(acc, r3, vv, tbl);
            acc_edge(acc, r4, vv, tbl);
            acc_edge(acc, r5, vv, tbl);
            acc_edge(acc, r6, vv, tbl);
            acc_edge(acc, r7, vv, tbl);
        }
        for (; j < m; j++) {
            int s0 = __shfl_sync(0xFFFFFFFFu, id, j);
            uint2 r0 = ((const uint2*)(g_uh + (size_t)s0 * H))[lane];
            acc_edge(acc, r0, vv, tbl);
        }
    }
    ((float4*)(g_hsum + hoff))[lane] = acc;
}

// ---------------- fused per-layer node kernel: BM=64, 2 CTAs/SM, 32x32 warp tiles ----------------
// smem: [0, 34816) A split | [34816, 104448) B split (Cs fp32 aliases here) | [104448, 108544) W2s
#define P2_OFF_B   34816
#define P2_OFF_W2S 104448
#define P2_SMEM    108544

__global__ __launch_bounds__(256, 2) void k_p2(
    int l, const float* __restrict__ nb1, const float* __restrict__ nb2,
    int w_nW1a, int w_nW2, int w_comb, int w_uv_next,
    const float* __restrict__ db1, const float* __restrict__ dW2,
    const float* __restrict__ db2, float* __restrict__ out) {
    extern __shared__ char smc[];
    bf* Ahi = (bf*)smc;                        // 64 x LDB
    bf* Alo = Ahi + 64 * LDB;
    bf* Bhi = (bf*)(smc + P2_OFF_B);           // 128 x LDB
    bf* Blo = Bhi + 128 * LDB;
    float* Cs  = (float*)(smc + P2_OFF_B);     // 64 x LDC, ALIASES B (used only between gemms)
    float* W2s = (float*)(smc + P2_OFF_W2S);   // 128 x 8
    int tid = threadIdx.x, wid = tid >> 5, wr = wid >> 2, wc = wid & 3;
    int row0 = blockIdx.x * 64;

    // Stage A: acc = h@nW1a
    loadsplit_A<64>(Ahi, Alo, g_h + (size_t)row0 * H, tid);
    copy_Bw(Bhi, Blo, w_nW1a, tid);
    __syncthreads();
    FC acc[2][2];
    fillp2(acc);
    gemm_p2(acc, Ahi, Alo, Bhi, Blo, wr, wc);
    __syncthreads();
    // Stage B: acc += hsum@Wcomb
    loadsplit_A<64>(Ahi, Alo, g_hsum + (size_t)row0 * H, tid);
    copy_Bw(Bhi, Blo, w_comb, tid);
    __syncthreads();
    gemm_p2(acc, Ahi, Alo, Bhi, Blo, wr, wc);
    __syncthreads();                            // done reading B -> Cs may overwrite
    store_p2s(Cs, acc, wr, wc);
    __syncthreads();
    // G = gelu(acc + deg*bcomb + nb1) -> A split
    for (int i = tid; i < 64 * 32; i += 256) {
        int r = i >> 5, c4 = (i & 31) << 2;
        int n = row0 + r;
        float d = (n < NN) ? (float)(g_rowptr[n + 1] - g_rowptr[n]) : 0.f;
        float4 v  = *(float4*)(Cs + r * LDC + c4);
        float4 bc = *(const float4*)(g_bcomb + l * H + c4);
        float4 b1 = *(const float4*)(nb1 + c4);
        v.x = gelu_f(v.x + d * bc.x + b1.x);
        v.y = gelu_f(v.y + d * bc.y + b1.y);
        v.z = gelu_f(v.z + d * bc.z + b1.z);
        v.w = gelu_f(v.w + d * bc.w + b1.w);
        split_smem4(Ahi, Alo, r * LDB + c4, v);
    }
    __syncthreads();                            // Cs read done -> B may overwrite
    // Stage C: upd = G@nW2
    copy_Bw(Bhi, Blo, w_nW2, tid);
    __syncthreads();
    fillp2(acc);
    gemm_p2(acc, Ahi, Alo, Bhi, Blo, wr, wc);
    __syncthreads();
    store_p2s(Cs, acc, wr, wc);
    __syncthreads();
    // hnew = h + upd + nb2 -> g_h, A split
    for (int i = tid; i < 64 * 32; i += 256) {
        int r = i >> 5, c4 = (i & 31) << 2;
        size_t off = (size_t)(row0 + r) * H + c4;
        float4 v  = *(float4*)(Cs + r * LDC + c4);
        float4 ho = *(const float4*)(g_h + off);
        float4 b2 = *(const float4*)(nb2 + c4);
        v.x += ho.x + b2.x; v.y += ho.y + b2.y;
        v.z += ho.z + b2.z; v.w += ho.w + b2.w;
        *(float4*)(g_h + off) = v;
        split_smem4(Ahi, Alo, r * LDB + c4, v);
    }
    __syncthreads();

    if (w_uv_next >= 0) {
        // u = hnew@eW1a -> g_uh (half)
        copy_Bw(Bhi, Blo, w_uv_next, tid);
        __syncthreads();
        FC a2[2][2];
        fillp2(a2);
        gemm_p2(a2, Ahi, Alo, Bhi, Blo, wr, wc);
        __syncthreads();                        // all warps done reading B
        store_p2s(Cs, a2, wr, wc);
        __syncthreads();
        cvt_C_to_uh(Cs, row0, tid);
        __syncthreads();                        // convert reads done -> B may overwrite
        // v = hnew@eW1b -> g_v (fp32)
        copy_Bw(Bhi, Blo, w_uv_next + 1, tid);
        __syncthreads();
        fillp2(a2);
        gemm_p2(a2, Ahi, Alo, Bhi, Blo, wr, wc);
        store_p2g(g_v, row0, a2, wr, wc);
    } else {
        // decode: hid = gelu(hnew@dW1 + db1); out = hid@dW2 + db2
        copy_Bw(Bhi, Blo, W_DECW1, tid);
        for (int i = tid; i < H * DOUT / 4; i += 256)
            *(float4*)(W2s + i * 4) = *(const float4*)(dW2 + i * 4);
        __syncthreads();
        fillp2(acc);
        gemm_p2(acc, Ahi, Alo, Bhi, Blo, wr, wc);
        __syncthreads();
        store_p2s(Cs, acc, wr, wc);
        __syncthreads();
        for (int i = tid; i < 64 * H; i += 256) {
            int r = i >> 7, c = i & 127;
            Cs[r * LDC + c] = gelu_f(Cs[r * LDC + c] + __ldg(db1 + c));
        }
        __syncthreads();
        for (int i = tid; i < 64 * DOUT; i += 256) {
            int r = i >> 3, o = i & 7;
            int n = row0 + r;
            if (n >= NN) continue;
            float a = __ldg(db2 + o);
            #pragma unroll 16
            for (int k = 0; k < H; k++) a += Cs[r * LDC + k] * W2s[k * DOUT + o];
            out[n * DOUT + o] = a;
        }
    }
}

// ---------------- launch ----------------
#define ENC_SMEM  ((64*DIN + DIN*H + 64*LDC) * 4 + (2*64 + 2*128) * LDB * 2)
#define COMB_SMEM (2 * 16384 * 4)

extern "C" void kernel_launch(void* const* d_in, const int* in_sizes, int n_in,
                              void* d_out, int out_size) {
    const float* x     = (const float*)d_in[0];
    const int*   ei    = (const int*)d_in[1];
    const float* encW1 = (const float*)d_in[2];
    const float* encb1 = (const float*)d_in[3];
    const float* encW2 = (const float*)d_in[4];
    const float* encb2 = (const float*)d_in[5];
    const float* eW1   = (const float*)d_in[6];
    const float* eb1   = (const float*)d_in[7];
    const float* eW2   = (const float*)d_in[8];
    const float* eb2   = (const float*)d_in[9];
    const float* nW1   = (const float*)d_in[10];
    const float* nb1   = (const float*)d_in[11];
    const float* nW2   = (const float*)d_in[12];
    const float* nb2   = (const float*)d_in[13];
    const float* dW1   = (const float*)d_in[14];
    const float* db1   = (const float*)d_in[15];
    const float* dW2   = (const float*)d_in[16];
    const float* db2   = (const float*)d_in[17];
    float* out = (float*)d_out;

    cudaFuncSetAttribute(k_encode, cudaFuncAttributeMaxDynamicSharedMemorySize, ENC_SMEM);
    cudaFuncSetAttribute(k_p2,     cudaFuncAttributeMaxDynamicSharedMemorySize, P2_SMEM);
    cudaFuncSetAttribute(k_comb,   cudaFuncAttributeMaxDynamicSharedMemorySize, COMB_SMEM);

    const int* src = ei;
    const int* dst = ei + NE;

    k_count<<<(NE + 255) / 256, 256>>>(dst);
    k_scan<<<1, 1024>>>();
    k_fill<<<(NE + 255) / 256, 256>>>(src, dst);

    k_tbl<<<(TBL_N + 255) / 256, 256>>>();

    WSrc ws{encW2, eW1, nW1, nW2, dW1};
    k_split_w<<<(NW_SPLIT * 16384 + 255) / 256, 256>>>(ws);

    k_encode<<<NPAD / 64, 256, ENC_SMEM>>>(x, encW1, encb1, encb2);

    for (int l = 0; l < NL; l++) {
        k_edge<<<NPAD / 8, 256>>>(eb1 + (size_t)l * H);
        if (l == 0) k_comb<<<NL, 256, COMB_SMEM>>>(eW2, nW1, eb2);
        bool last = (l == NL - 1);
        k_p2<<<NPAD / 64, 256, P2_SMEM>>>(
            l, nb1 + (size_t)l * H, nb2 + (size_t)l * H,
            W_NW1A(l), W_NW2(l), W_COMB(l),
            last ? -1 : W_EW1(l + 1, 0),
            db1, dW2, db2, out);
    }
}